// round 8
// baseline (speedup 1.0000x reference)
#include <cuda_runtime.h>
#include <cuda_bf16.h>
#include <stdint.h>
#include <math.h>

#define D        27
#define QB       512
#define NCLS     11
#define KNN      3
#define SLABS    148
#define TILE     64
#define RPITCH   192                  // bytes per formatted row (3 k16-block pairs)
#define TBYTES   (TILE * RPITCH)      // 12288 per tile
#define NPMAX    409600
#define SMEM_TOT (2 * TBYTES + 128)

// ---------------- static device scratch ------------------------------------
__device__ unsigned int g_scale_bits[D];
__device__ float        g_inv[D];
__device__ float        g_qm[QB * D];     // -2 * scaled query
__device__ float        g_qn[QB];
__device__ float2       g_part[(size_t)QB * SLABS * KNN];
__device__ __align__(16) uint8_t g_btiles[(size_t)NPMAX * RPITCH];

// ---------------- helpers ----------------------------------------------------
__device__ __forceinline__ uint32_t smem_u32(const void* p) {
    uint32_t a;
    asm("{ .reg .u64 t; cvta.to.shared.u64 t, %1; cvt.u32.u64 %0, t; }" : "=r"(a) : "l"(p));
    return a;
}
__device__ __forceinline__ void lds128(uint32_t& x, uint32_t& y, uint32_t& z, uint32_t& w, uint32_t a) {
    asm volatile("ld.shared.v4.b32 {%0,%1,%2,%3}, [%4];"
                 : "=r"(x), "=r"(y), "=r"(z), "=r"(w) : "r"(a));
}
__device__ __forceinline__ void sts128(uint32_t a, uint32_t w0, uint32_t w1, uint32_t w2, uint32_t w3) {
    asm volatile("st.shared.v4.b32 [%0], {%1,%2,%3,%4};"
                 :: "r"(a), "r"(w0), "r"(w1), "r"(w2), "r"(w3) : "memory");
}
__device__ __forceinline__ void cpa16(uint32_t s, const void* g) {
    asm volatile("cp.async.cg.shared.global [%0], [%1], 16;" :: "r"(s), "l"(g) : "memory");
}
#define CP_COMMIT() asm volatile("cp.async.commit_group;" ::: "memory")
#define CP_WAIT0()  asm volatile("cp.async.wait_group 0;" ::: "memory")

__device__ __forceinline__ uint32_t pk(__nv_bfloat16 a, __nv_bfloat16 b) {
    unsigned short x = *(unsigned short*)&a, y = *(unsigned short*)&b;
    return (uint32_t)x | ((uint32_t)y << 16);
}

#define MMA(d0,d1,d2,d3, A0,A1,A2,A3, B0,B1) \
    asm volatile("mma.sync.aligned.m16n8k16.row.col.f32.bf16.bf16.f32 " \
        "{%0,%1,%2,%3}, {%4,%5,%6,%7}, {%8,%9}, {%0,%1,%2,%3};" \
        : "+f"(d0), "+f"(d1), "+f"(d2), "+f"(d3) \
        : "r"(A0), "r"(A1), "r"(A2), "r"(A3), "r"(B0), "r"(B1))

#define MMA0(d0,d1,d2,d3, A0,A1,A2,A3, B0,B1) \
    asm volatile("mma.sync.aligned.m16n8k16.row.col.f32.bf16.bf16.f32 " \
        "{%0,%1,%2,%3}, {%4,%5,%6,%7}, {%8,%9}, {%10,%11,%12,%13};" \
        : "=f"(d0), "=f"(d1), "=f"(d2), "=f"(d3) \
        : "r"(A0), "r"(A1), "r"(A2), "r"(A3), "r"(B0), "r"(B1), \
          "f"(0.f), "f"(0.f), "f"(0.f), "f"(0.f))

// ---------------- small kernels ----------------------------------------------
__global__ void k_init() { if (threadIdx.x < D) g_scale_bits[threadIdx.x] = 0u; }

__global__ void k_scale(const float* __restrict__ tf, int n) {
    __shared__ unsigned int sm[D];
    if (threadIdx.x < D) sm[threadIdx.x] = 0u;
    __syncthreads();
    int i = blockIdx.x * blockDim.x + threadIdx.x;
    int col = i % D;
    int stride = gridDim.x * blockDim.x;   // multiple of 27
    float m = 0.f;
    for (; i < n; i += stride) m = fmaxf(m, fabsf(tf[i]));
    atomicMax(&sm[col], __float_as_uint(m));
    __syncthreads();
    if (threadIdx.x < D) atomicMax(&g_scale_bits[threadIdx.x], sm[threadIdx.x]);
}

__global__ void k_query(const float* __restrict__ q) {
    __shared__ float inv[D];
    int t = threadIdx.x;
    if (t < D) {
        float s = __uint_as_float(g_scale_bits[t]);
        float v = (s != 0.f) ? (1.f / s) : 0.f;
        inv[t] = v;
        g_inv[t] = v;
    }
    __syncthreads();
    float qn = 0.f;
    #pragma unroll
    for (int d = 0; d < D; ++d) {
        float v = q[t * D + d] * inv[d];
        qn = fmaf(v, v, qn);
        g_qm[t * D + d] = -2.f * v;
    }
    g_qn[t] = qn;
}

// ---------------- k_prep: format train set once (192 B per point) -------------
// Blocks: s0=hi[0:16] s1=hi[16:27]+xnh@k27+xnl@k28  s2=hi[0:16] s3=hi[16:27]
//         s4=lo[0:16] s5=lo[16:27]; pair p at byte p*64;
// chunk c of a pair = {we[c], we[c+4], wo[c], wo[c+4]}.
// 3-phase for full coalescing: staged load -> register pack -> smem-transposed
// coalesced STG.128 stream.
__global__ void __launch_bounds__(128) k_prep(const float* __restrict__ tf, int N, int NP) {
    __shared__ float st[128 * 28];
    __shared__ uint4 pkm[128 * 12];
    __shared__ float inv[D];
    const int tid = threadIdx.x;
    const int p0  = blockIdx.x * 128;
    if (tid < D) inv[tid] = g_inv[tid];
    __syncthreads();

    // phase 1: coalesced load + scale into staging
    const int nval = min(128 * D, (N - p0) * D);
    for (int i = tid; i < 128 * D; i += 128) {
        float v = 0.f;
        if (i < nval) v = tf[(size_t)p0 * D + i];
        int r = i / D, d = i - r * D;
        st[r * 28 + d] = v * inv[d];
    }
    __syncthreads();

    // phase 2: per-thread convert + pack (thread tid owns point p0+tid)
    const int p = p0 + tid;
    float v[27];
    float xn = 0.f;
    #pragma unroll
    for (int d = 0; d < D; ++d) {
        float x = st[tid * 28 + d];
        v[d] = x;
        xn = fmaf(x, x, xn);
    }
    if (p >= N) xn = 1e30f;     // padding rows never win top-3

    __nv_bfloat16 hb[27], lb[27];
    #pragma unroll
    for (int d = 0; d < D; ++d) {
        hb[d] = __float2bfloat16(v[d]);
        lb[d] = __float2bfloat16(v[d] - __bfloat162float(hb[d]));
    }
    const __nv_bfloat16 zr = __float2bfloat16(0.f);
    __nv_bfloat16 xh = __float2bfloat16(xn);
    __nv_bfloat16 xl = __float2bfloat16(xn - __bfloat162float(xh));

    uint32_t hw0[8], lw0[8], s1b[8], s3b[8], s5b[8];
    #pragma unroll
    for (int j = 0; j < 8; ++j) {
        hw0[j] = pk(hb[2*j], hb[2*j+1]);
        lw0[j] = pk(lb[2*j], lb[2*j+1]);
    }
    #pragma unroll
    for (int j = 0; j < 5; ++j) {
        s1b[j] = pk(hb[16+2*j], hb[17+2*j]);
        s3b[j] = s1b[j];
        s5b[j] = pk(lb[16+2*j], lb[17+2*j]);
    }
    s1b[5] = pk(hb[26], xh); s1b[6] = pk(xl, zr); s1b[7] = 0;
    s3b[5] = pk(hb[26], zr); s3b[6] = 0;          s3b[7] = 0;
    s5b[5] = pk(lb[26], zr); s5b[6] = 0;          s5b[7] = 0;

    uint4 my[12];
    #pragma unroll
    for (int c = 0; c < 4; ++c) {
        my[c]     = make_uint4(hw0[c], hw0[c+4], s1b[c], s1b[c+4]);  // pair (s0,s1)
        my[4 + c] = make_uint4(hw0[c], hw0[c+4], s3b[c], s3b[c+4]);  // pair (s2,s3)
        my[8 + c] = make_uint4(lw0[c], lw0[c+4], s5b[c], s5b[c+4]);  // pair (s4,s5)
    }
    #pragma unroll
    for (int i = 0; i < 12; ++i) pkm[tid * 12 + i] = my[i];
    __syncthreads();

    // phase 3: fully-coalesced STG.128 stream of the block's 24 KB
    const int npts = min(128, NP - p0);
    if (npts > 0) {
        uint4* gd = (uint4*)(g_btiles + (size_t)p0 * RPITCH);
        const int tot = npts * 12;
        for (int i = tid; i < tot; i += 128) gd[i] = pkm[i];
    }
}

// ---------------- main HMMA kernel (R5-arch, deep chains) ---------------------
__global__ void __launch_bounds__(128, 4)
k_hmma(int N) {
    extern __shared__ char smraw[];
    const uint32_t smb = smem_u32(smraw);
    const int tid  = threadIdx.x;
    const int w    = tid >> 5;
    const int lane = tid & 31;
    const int g    = lane >> 2;
    const int c    = lane & 3;
    const int qg   = blockIdx.x & 3;
    const int slab = blockIdx.x >> 2;
    const int qbase = qg * 128;
    const int nt = (N + TILE - 1) / TILE;

    // ---- stage A rows (128 queries) into the B region, 192B pair layout
    {
        const int q = qbase + tid;
        __nv_bfloat16 hi_[27], lo_[27];
        #pragma unroll
        for (int d = 0; d < D; ++d) {
            float v = g_qm[q * D + d];
            __nv_bfloat16 h = __float2bfloat16(v);
            hi_[d] = h;
            lo_[d] = __float2bfloat16(v - __bfloat162float(h));
        }
        const __nv_bfloat16 one = __float2bfloat16(1.f);
        const __nv_bfloat16 zr  = __float2bfloat16(0.f);
        uint32_t hw[8], lw[8], b1[8], b3[8], b5[8];
        #pragma unroll
        for (int j = 0; j < 8; ++j) {
            hw[j] = pk(hi_[2*j], hi_[2*j+1]);
            lw[j] = pk(lo_[2*j], lo_[2*j+1]);
        }
        #pragma unroll
        for (int j = 0; j < 5; ++j) {
            b1[j] = pk(hi_[16+2*j], hi_[17+2*j]);
            b5[j] = b1[j];
            b3[j] = pk(lo_[16+2*j], lo_[17+2*j]);
        }
        b1[5] = pk(hi_[26], one); b1[6] = pk(one, zr); b1[7] = 0;  // ones pick up xn
        b3[5] = pk(lo_[26], zr);  b3[6] = 0;           b3[7] = 0;
        b5[5] = pk(hi_[26], zr);  b5[6] = 0;           b5[7] = 0;
        const uint32_t rowa = smb + tid * RPITCH;
        #pragma unroll
        for (int cc = 0; cc < 4; ++cc) {
            sts128(rowa +       cc*16, hw[cc], hw[cc+4], b1[cc], b1[cc+4]); // (s0,s1)
            sts128(rowa +  64 + cc*16, lw[cc], lw[cc+4], b3[cc], b3[cc+4]); // (s2,s3)
            sts128(rowa + 128 + cc*16, hw[cc], hw[cc+4], b5[cc], b5[cc+4]); // (s4,s5)
        }
    }
    __syncthreads();

    // ---- load persistent A fragments (6 sets x 2 m-tiles)
    uint32_t a0[2][6], a1[2][6], a2[2][6], a3[2][6];
    #pragma unroll
    for (int mt = 0; mt < 2; ++mt)
        #pragma unroll
        for (int pp = 0; pp < 3; ++pp) {
            const uint32_t base = smb + (uint32_t)(w * 32 + mt * 16 + g) * RPITCH + pp * 64 + c * 16;
            lds128(a0[mt][2*pp], a2[mt][2*pp], a0[mt][2*pp+1], a2[mt][2*pp+1], base);
            lds128(a1[mt][2*pp], a3[mt][2*pp], a1[mt][2*pp+1], a3[mt][2*pp+1], base + 8 * RPITCH);
        }
    __syncthreads();

    const float INF = __int_as_float(0x7f800000);
    float t0[4], t1[4], t2[4];
    int   i0[4], i1[4], i2[4];
    #pragma unroll
    for (int s = 0; s < 4; ++s) { t0[s]=t1[s]=t2[s]=INF; i0[s]=i1[s]=i2[s]=0; }

    #define INS(v_, idx_, s_) do { \
        float _v = (v_); \
        if (_v < t2[s_]) { \
            int _ix = (idx_); \
            if (_v < t1[s_]) { \
                t2[s_] = t1[s_]; i2[s_] = i1[s_]; \
                if (_v < t0[s_]) { t1[s_]=t0[s_]; i1[s_]=i0[s_]; t0[s_]=_v; i0[s_]=_ix; } \
                else             { t1[s_]=_v; i1[s_]=_ix; } \
            } else { t2[s_] = _v; i2[s_] = _ix; } \
        } } while (0)
    #define INS2(da_, db_, s_) do { \
        if (fminf(da_, db_) < t2[s_]) { INS(da_, idx0, s_); INS(db_, idx0 + 1, s_); } } while (0)

    // ---- prologue copy (12 KB tile: 6 x cp.async.16 per thread)
    if (slab < nt) {
        const uint8_t* src = g_btiles + (size_t)slab * TBYTES;
        #pragma unroll
        for (int i = 0; i < 6; ++i) cpa16(smb + tid * 16 + i * 2048, src + tid * 16 + i * 2048);
    }
    CP_COMMIT();

    int it = 0;
    for (int t = slab; t < nt; t += SLABS, ++it) {
        CP_WAIT0();
        __syncthreads();
        const int buf = it & 1;
        const uint32_t bufb = smb + (uint32_t)buf * TBYTES;
        const int tn = t + SLABS;
        if (tn < nt) {
            const uint32_t dstb = smb + (uint32_t)(buf ^ 1) * TBYTES;
            const uint8_t* src = g_btiles + (size_t)tn * TBYTES;
            #pragma unroll
            for (int i = 0; i < 6; ++i) cpa16(dstb + tid * 16 + i * 2048, src + tid * 16 + i * 2048);
        }
        CP_COMMIT();

        const int tb = t * TILE;
        #pragma unroll 2
        for (int j = 0; j < 8; ++j) {
            const uint32_t bb = bufb + (uint32_t)(j * 8 + g) * RPITCH + c * 16;
            float d00,d01,d02,d03, d10,d11,d12,d13;
            uint32_t e0,e1,o0,o1;
            lds128(e0, e1, o0, o1, bb);                  // s0, s1
            MMA0(d00,d01,d02,d03, a0[0][0],a1[0][0],a2[0][0],a3[0][0], e0,e1);
            MMA0(d10,d11,d12,d13, a0[1][0],a1[1][0],a2[1][0],a3[1][0], e0,e1);
            MMA (d00,d01,d02,d03, a0[0][1],a1[0][1],a2[0][1],a3[0][1], o0,o1);
            MMA (d10,d11,d12,d13, a0[1][1],a1[1][1],a2[1][1],a3[1][1], o0,o1);
            lds128(e0, e1, o0, o1, bb + 64);             // s2, s3
            MMA (d00,d01,d02,d03, a0[0][2],a1[0][2],a2[0][2],a3[0][2], e0,e1);
            MMA (d10,d11,d12,d13, a0[1][2],a1[1][2],a2[1][2],a3[1][2], e0,e1);
            MMA (d00,d01,d02,d03, a0[0][3],a1[0][3],a2[0][3],a3[0][3], o0,o1);
            MMA (d10,d11,d12,d13, a0[1][3],a1[1][3],a2[1][3],a3[1][3], o0,o1);
            lds128(e0, e1, o0, o1, bb + 128);            // s4, s5
            MMA (d00,d01,d02,d03, a0[0][4],a1[0][4],a2[0][4],a3[0][4], e0,e1);
            MMA (d10,d11,d12,d13, a0[1][4],a1[1][4],a2[1][4],a3[1][4], e0,e1);
            MMA (d00,d01,d02,d03, a0[0][5],a1[0][5],a2[0][5],a3[0][5], o0,o1);
            MMA (d10,d11,d12,d13, a0[1][5],a1[1][5],a2[1][5],a3[1][5], o0,o1);

            const int idx0 = tb + j * 8 + 2 * c;
            INS2(d00, d01, 0);
            INS2(d02, d03, 1);
            INS2(d10, d11, 2);
            INS2(d12, d13, 3);
        }
        __syncthreads();
    }
    #undef INS2
    #undef INS

    // ---- merge top-3 across the 4 lanes of each quad (same queries, disjoint cols)
    #pragma unroll
    for (int s = 0; s < 4; ++s) {
        #pragma unroll
        for (int off = 2; off > 0; off >>= 1) {
            float o0 = __shfl_down_sync(0xffffffffu, t0[s], off);
            float o1 = __shfl_down_sync(0xffffffffu, t1[s], off);
            float o2 = __shfl_down_sync(0xffffffffu, t2[s], off);
            int   z0 = __shfl_down_sync(0xffffffffu, i0[s], off);
            int   z1 = __shfl_down_sync(0xffffffffu, i1[s], off);
            int   z2 = __shfl_down_sync(0xffffffffu, i2[s], off);
            #define MINS(vv, zz) do { \
                float _v = (vv); int _z = (zz); \
                if (_v < t2[s] || (_v == t2[s] && _z < i2[s])) { \
                    if (_v < t1[s] || (_v == t1[s] && _z < i1[s])) { \
                        t2[s]=t1[s]; i2[s]=i1[s]; \
                        if (_v < t0[s] || (_v == t0[s] && _z < i0[s])) { t1[s]=t0[s]; i1[s]=i0[s]; t0[s]=_v; i0[s]=_z; } \
                        else { t1[s]=_v; i1[s]=_z; } \
                    } else { t2[s]=_v; i2[s]=_z; } \
                } } while (0)
            MINS(o0, z0); MINS(o1, z1); MINS(o2, z2);
            #undef MINS
        }
    }
    if ((lane & 3) == 0) {
        #pragma unroll
        for (int s = 0; s < 4; ++s) {
            const int q = qbase + w * 32 + (s >> 1) * 16 + g + (s & 1) * 8;
            float2* o = g_part + ((size_t)q * SLABS + slab) * KNN;
            o[0] = make_float2(t0[s], __int_as_float(i0[s]));
            o[1] = make_float2(t1[s], __int_as_float(i1[s]));
            o[2] = make_float2(t2[s], __int_as_float(i2[s]));
        }
    }
}

// ---------------- merge + vote -------------------------------------------------
__device__ __forceinline__ void ins3(float v, int ix,
                                     float& r0, int& y0, float& r1, int& y1,
                                     float& r2, int& y2) {
    if (v < r2 || (v == r2 && ix < y2)) {
        if (v < r1 || (v == r1 && ix < y1)) {
            r2 = r1; y2 = y1;
            if (v < r0 || (v == r0 && ix < y0)) { r1 = r0; y1 = y0; r0 = v; y0 = ix; }
            else                                 { r1 = v;  y1 = ix; }
        } else { r2 = v; y2 = ix; }
    }
}

__global__ void k_reduce(const float* __restrict__ labels, float* __restrict__ out) {
    const int q    = blockIdx.x;
    const int tid  = threadIdx.x;   // 128
    const int lane = tid & 31;
    const int wid  = tid >> 5;
    __shared__ float sd[12];
    __shared__ int   si[12];
    const float INF = __int_as_float(0x7f800000);

    float b0 = INF, b1 = INF, b2 = INF;
    int   x0 = 0,   x1 = 0,   x2 = 0;
    const float2* p = g_part + (size_t)q * SLABS * KNN;
    for (int e = tid; e < SLABS * KNN; e += 128) {
        float2 v = p[e];
        ins3(v.x, __float_as_int(v.y), b0, x0, b1, x1, b2, x2);
    }
    #pragma unroll
    for (int off = 16; off > 0; off >>= 1) {
        float o0 = __shfl_down_sync(0xffffffffu, b0, off);
        float o1 = __shfl_down_sync(0xffffffffu, b1, off);
        float o2 = __shfl_down_sync(0xffffffffu, b2, off);
        int   z0 = __shfl_down_sync(0xffffffffu, x0, off);
        int   z1 = __shfl_down_sync(0xffffffffu, x1, off);
        int   z2 = __shfl_down_sync(0xffffffffu, x2, off);
        ins3(o0, z0, b0, x0, b1, x1, b2, x2);
        ins3(o1, z1, b0, x0, b1, x1, b2, x2);
        ins3(o2, z2, b0, x0, b1, x1, b2, x2);
    }
    if (lane == 0) {
        sd[wid * 3 + 0] = b0; si[wid * 3 + 0] = x0;
        sd[wid * 3 + 1] = b1; si[wid * 3 + 1] = x1;
        sd[wid * 3 + 2] = b2; si[wid * 3 + 2] = x2;
    }
    __syncthreads();

    if (tid == 0) {
        float r0 = sd[0], r1 = sd[1], r2 = sd[2];
        int   y0 = si[0], y1 = si[1], y2 = si[2];
        #pragma unroll
        for (int e = 3; e < 12; ++e) ins3(sd[e], si[e], r0, y0, r1, y1, r2, y2);

        const float qn = g_qn[q];
        const float kd0 = sqrtf(fmaxf(r0 + qn, 0.f));
        const float kd1 = sqrtf(fmaxf(r1 + qn, 0.f));
        const float kd2 = sqrtf(fmaxf(r2 + qn, 0.f));
        out[q * KNN + 0] = kd0;
        out[q * KNN + 1] = kd1;
        out[q * KNN + 2] = kd2;

        const float w0 = (kd0 == 0.f) ? 1.f : kd0;
        const float w1 = (kd1 == 0.f) ? 1.f : kd1;
        const float w2 = (kd2 == 0.f) ? 1.f : kd2;
        const float* l0 = labels + (size_t)y0 * NCLS;
        const float* l1 = labels + (size_t)y1 * NCLS;
        const float* l2 = labels + (size_t)y2 * NCLS;

        float votes[NCLS];
        #pragma unroll
        for (int cc = 0; cc < NCLS; ++cc)
            votes[cc] = l0[cc] / w0 + l1[cc] / w1 + l2[cc] / w2;

        int am = 0; float bm = votes[0];
        #pragma unroll
        for (int cc = 1; cc < NCLS; ++cc)
            if (votes[cc] > bm) { bm = votes[cc]; am = cc; }

        const bool zero_hit = (kd0 == 0.f);
        float* ro = out + QB * KNN + q * NCLS;
        #pragma unroll
        for (int cc = 0; cc < NCLS; ++cc)
            ro[cc] = zero_hit ? l0[cc] : ((cc == am) ? 1.f : 0.f);
    }
}

// ---------------- launch --------------------------------------------------------
extern "C" void kernel_launch(void* const* d_in, const int* in_sizes, int n_in,
                              void* d_out, int out_size) {
    const float* query = (const float*)d_in[0];
    const float* tf    = (const float*)d_in[1];
    const float* tl    = (const float*)d_in[2];
    float* out = (float*)d_out;
    const int n_elems = in_sizes[1];
    const int N = n_elems / D;
    const int nt = (N + TILE - 1) / TILE;
    const int NP = nt * TILE;

    k_init  <<<1,   32 >>>();
    k_scale <<<888, 216>>>(tf, n_elems);
    k_query <<<1,   QB >>>(query);
    k_prep  <<<(NP + 127) / 128, 128>>>(tf, N, NP);
    k_hmma  <<<SLABS * 4, 128, SMEM_TOT>>>(N);
    k_reduce<<<QB,  128>>>(tl, out);
}

// round 9
// speedup vs baseline: 1.0278x; 1.0278x over previous
#include <cuda_runtime.h>
#include <cuda_bf16.h>
#include <stdint.h>
#include <math.h>

#define D        27
#define QB       512
#define NCLS     11
#define KNN      3
#define SLABS    148
#define GROUPS   8                    // query groups of 64
#define TILE     64
#define RPITCH   192                  // bytes per formatted row (3 k16-block pairs)
#define TBYTES   (TILE * RPITCH)      // 12288 per tile
#define NPMAX    409600
#define SMEM_TOT (2 * TBYTES + 128)

// ---------------- static device scratch ------------------------------------
__device__ unsigned int g_scale_bits[D];
__device__ float        g_inv[D];
__device__ float        g_qm[QB * D];     // -2 * scaled query
__device__ float        g_qn[QB];
__device__ float2       g_part[(size_t)QB * SLABS * KNN];
__device__ __align__(16) uint8_t g_btiles[(size_t)NPMAX * RPITCH];

// ---------------- helpers ----------------------------------------------------
__device__ __forceinline__ uint32_t smem_u32(const void* p) {
    uint32_t a;
    asm("{ .reg .u64 t; cvta.to.shared.u64 t, %1; cvt.u32.u64 %0, t; }" : "=r"(a) : "l"(p));
    return a;
}
__device__ __forceinline__ void lds128(uint32_t& x, uint32_t& y, uint32_t& z, uint32_t& w, uint32_t a) {
    asm volatile("ld.shared.v4.b32 {%0,%1,%2,%3}, [%4];"
                 : "=r"(x), "=r"(y), "=r"(z), "=r"(w) : "r"(a));
}
__device__ __forceinline__ void sts128(uint32_t a, uint32_t w0, uint32_t w1, uint32_t w2, uint32_t w3) {
    asm volatile("st.shared.v4.b32 [%0], {%1,%2,%3,%4};"
                 :: "r"(a), "r"(w0), "r"(w1), "r"(w2), "r"(w3) : "memory");
}
__device__ __forceinline__ void cpa16(uint32_t s, const void* g) {
    asm volatile("cp.async.cg.shared.global [%0], [%1], 16;" :: "r"(s), "l"(g) : "memory");
}
#define CP_COMMIT() asm volatile("cp.async.commit_group;" ::: "memory")
#define CP_WAIT0()  asm volatile("cp.async.wait_group 0;" ::: "memory")

__device__ __forceinline__ uint32_t pk(__nv_bfloat16 a, __nv_bfloat16 b) {
    unsigned short x = *(unsigned short*)&a, y = *(unsigned short*)&b;
    return (uint32_t)x | ((uint32_t)y << 16);
}

#define MMA(d0,d1,d2,d3, A0,A1,A2,A3, B0,B1) \
    asm volatile("mma.sync.aligned.m16n8k16.row.col.f32.bf16.bf16.f32 " \
        "{%0,%1,%2,%3}, {%4,%5,%6,%7}, {%8,%9}, {%0,%1,%2,%3};" \
        : "+f"(d0), "+f"(d1), "+f"(d2), "+f"(d3) \
        : "r"(A0), "r"(A1), "r"(A2), "r"(A3), "r"(B0), "r"(B1))

#define MMA0(d0,d1,d2,d3, A0,A1,A2,A3, B0,B1) \
    asm volatile("mma.sync.aligned.m16n8k16.row.col.f32.bf16.bf16.f32 " \
        "{%0,%1,%2,%3}, {%4,%5,%6,%7}, {%8,%9}, {%10,%11,%12,%13};" \
        : "=f"(d0), "=f"(d1), "=f"(d2), "=f"(d3) \
        : "r"(A0), "r"(A1), "r"(A2), "r"(A3), "r"(B0), "r"(B1), \
          "f"(0.f), "f"(0.f), "f"(0.f), "f"(0.f))

// ---------------- small kernels ----------------------------------------------
__global__ void k_init() { if (threadIdx.x < D) g_scale_bits[threadIdx.x] = 0u; }

__global__ void k_scale(const float* __restrict__ tf, int n) {
    __shared__ unsigned int sm[D];
    if (threadIdx.x < D) sm[threadIdx.x] = 0u;
    __syncthreads();
    int i = blockIdx.x * blockDim.x + threadIdx.x;
    int col = i % D;
    int stride = gridDim.x * blockDim.x;   // multiple of 27
    float m = 0.f;
    for (; i < n; i += stride) m = fmaxf(m, fabsf(tf[i]));
    atomicMax(&sm[col], __float_as_uint(m));
    __syncthreads();
    if (threadIdx.x < D) atomicMax(&g_scale_bits[threadIdx.x], sm[threadIdx.x]);
}

__global__ void k_query(const float* __restrict__ q) {
    __shared__ float inv[D];
    int t = threadIdx.x;
    if (t < D) {
        float s = __uint_as_float(g_scale_bits[t]);
        float v = (s != 0.f) ? (1.f / s) : 0.f;
        inv[t] = v;
        g_inv[t] = v;
    }
    __syncthreads();
    float qn = 0.f;
    #pragma unroll
    for (int d = 0; d < D; ++d) {
        float v = q[t * D + d] * inv[d];
        qn = fmaf(v, v, qn);
        g_qm[t * D + d] = -2.f * v;
    }
    g_qn[t] = qn;
}

// ---------------- k_prep: format train set once (192 B per point) -------------
// Blocks: s0=hi[0:16] s1=hi[16:27]+xnh@k27+xnl@k28  s2=hi[0:16] s3=hi[16:27]
//         s4=lo[0:16] s5=lo[16:27]; pair p at byte p*64;
// chunk c of a pair = {we[c], we[c+4], wo[c], wo[c+4]}.
// Coalesced phase-1 read into smem; per-thread pack; direct STG.128 stream
// (each thread's 192B row is contiguous).
__global__ void __launch_bounds__(128) k_prep(const float* __restrict__ tf, int N, int NP) {
    __shared__ float st[128 * 28];
    __shared__ float inv[D];
    const int tid = threadIdx.x;
    const int p0  = blockIdx.x * 128;
    if (tid < D) inv[tid] = g_inv[tid];
    __syncthreads();

    // phase 1: coalesced load + scale into staging
    const int nval = min(128 * D, (N - p0) * D);
    for (int i = tid; i < 128 * D; i += 128) {
        float v = 0.f;
        if (i < nval) v = tf[(size_t)p0 * D + i];
        int r = i / D, d = i - r * D;
        st[r * 28 + d] = v * inv[d];
    }
    __syncthreads();

    // phase 2: per-thread convert + pack + direct store
    const int p = p0 + tid;
    if (p >= NP) return;
    float v[27];
    float xn = 0.f;
    #pragma unroll
    for (int d = 0; d < D; ++d) {
        float x = st[tid * 28 + d];
        v[d] = x;
        xn = fmaf(x, x, xn);
    }
    if (p >= N) xn = 1e30f;     // padding rows never win top-3

    __nv_bfloat16 hb[27], lb[27];
    #pragma unroll
    for (int d = 0; d < D; ++d) {
        hb[d] = __float2bfloat16(v[d]);
        lb[d] = __float2bfloat16(v[d] - __bfloat162float(hb[d]));
    }
    const __nv_bfloat16 zr = __float2bfloat16(0.f);
    __nv_bfloat16 xh = __float2bfloat16(xn);
    __nv_bfloat16 xl = __float2bfloat16(xn - __bfloat162float(xh));

    uint32_t hw0[8], lw0[8], s1b[8], s3b[8], s5b[8];
    #pragma unroll
    for (int j = 0; j < 8; ++j) {
        hw0[j] = pk(hb[2*j], hb[2*j+1]);
        lw0[j] = pk(lb[2*j], lb[2*j+1]);
    }
    #pragma unroll
    for (int j = 0; j < 5; ++j) {
        s1b[j] = pk(hb[16+2*j], hb[17+2*j]);
        s3b[j] = s1b[j];
        s5b[j] = pk(lb[16+2*j], lb[17+2*j]);
    }
    s1b[5] = pk(hb[26], xh); s1b[6] = pk(xl, zr); s1b[7] = 0;
    s3b[5] = pk(hb[26], zr); s3b[6] = 0;          s3b[7] = 0;
    s5b[5] = pk(lb[26], zr); s5b[6] = 0;          s5b[7] = 0;

    uint4* dst = (uint4*)(g_btiles + (size_t)p * RPITCH);
    #pragma unroll
    for (int c = 0; c < 4; ++c) {
        dst[c]     = make_uint4(hw0[c], hw0[c+4], s1b[c], s1b[c+4]);  // pair (s0,s1)
        dst[4 + c] = make_uint4(hw0[c], hw0[c+4], s3b[c], s3b[c+4]);  // pair (s2,s3)
        dst[8 + c] = make_uint4(lw0[c], lw0[c+4], s5b[c], s5b[c+4]);  // pair (s4,s5)
    }
}

// ---------------- main HMMA kernel: 1 m-tile/warp, 8 CTAs/SM -------------------
__global__ void __launch_bounds__(128, 8)
k_hmma(int N) {
    extern __shared__ char smraw[];
    const uint32_t smb = smem_u32(smraw);
    const int tid  = threadIdx.x;
    const int w    = tid >> 5;
    const int lane = tid & 31;
    const int g    = lane >> 2;
    const int c    = lane & 3;
    const int qg   = blockIdx.x & 7;
    const int slab = blockIdx.x >> 3;
    const int qbase = qg * 64;
    const int nt = (N + TILE - 1) / TILE;

    // ---- stage A rows (64 queries, threads 0-63), 192B pair layout
    if (tid < 64) {
        const int q = qbase + tid;
        __nv_bfloat16 hi_[27], lo_[27];
        #pragma unroll
        for (int d = 0; d < D; ++d) {
            float v = g_qm[q * D + d];
            __nv_bfloat16 h = __float2bfloat16(v);
            hi_[d] = h;
            lo_[d] = __float2bfloat16(v - __bfloat162float(h));
        }
        const __nv_bfloat16 one = __float2bfloat16(1.f);
        const __nv_bfloat16 zr  = __float2bfloat16(0.f);
        uint32_t hw[8], lw[8], b1[8], b3[8], b5[8];
        #pragma unroll
        for (int j = 0; j < 8; ++j) {
            hw[j] = pk(hi_[2*j], hi_[2*j+1]);
            lw[j] = pk(lo_[2*j], lo_[2*j+1]);
        }
        #pragma unroll
        for (int j = 0; j < 5; ++j) {
            b1[j] = pk(hi_[16+2*j], hi_[17+2*j]);
            b5[j] = b1[j];
            b3[j] = pk(lo_[16+2*j], lo_[17+2*j]);
        }
        b1[5] = pk(hi_[26], one); b1[6] = pk(one, zr); b1[7] = 0;  // ones pick up xn
        b3[5] = pk(lo_[26], zr);  b3[6] = 0;           b3[7] = 0;
        b5[5] = pk(hi_[26], zr);  b5[6] = 0;           b5[7] = 0;
        const uint32_t rowa = smb + tid * RPITCH;
        #pragma unroll
        for (int cc = 0; cc < 4; ++cc) {
            sts128(rowa +       cc*16, hw[cc], hw[cc+4], b1[cc], b1[cc+4]); // (s0,s1)
            sts128(rowa +  64 + cc*16, lw[cc], lw[cc+4], b3[cc], b3[cc+4]); // (s2,s3)
            sts128(rowa + 128 + cc*16, hw[cc], hw[cc+4], b5[cc], b5[cc+4]); // (s4,s5)
        }
    }
    __syncthreads();

    // ---- load persistent A fragments (6 s-blocks, one m16 tile per warp)
    uint32_t a0[6], a1[6], a2[6], a3[6];
    #pragma unroll
    for (int pp = 0; pp < 3; ++pp) {
        const uint32_t base = smb + (uint32_t)(w * 16 + g) * RPITCH + pp * 64 + c * 16;
        lds128(a0[2*pp], a2[2*pp], a0[2*pp+1], a2[2*pp+1], base);
        lds128(a1[2*pp], a3[2*pp], a1[2*pp+1], a3[2*pp+1], base + 8 * RPITCH);
    }
    __syncthreads();

    const float INF = __int_as_float(0x7f800000);
    float t0[2], t1[2], t2[2];
    int   i0[2], i1[2], i2[2];
    #pragma unroll
    for (int s = 0; s < 2; ++s) { t0[s]=t1[s]=t2[s]=INF; i0[s]=i1[s]=i2[s]=0; }

    #define INS(v_, idx_, s_) do { \
        float _v = (v_); \
        if (_v < t2[s_]) { \
            int _ix = (idx_); \
            if (_v < t1[s_]) { \
                t2[s_] = t1[s_]; i2[s_] = i1[s_]; \
                if (_v < t0[s_]) { t1[s_]=t0[s_]; i1[s_]=i0[s_]; t0[s_]=_v; i0[s_]=_ix; } \
                else             { t1[s_]=_v; i1[s_]=_ix; } \
            } else { t2[s_] = _v; i2[s_] = _ix; } \
        } } while (0)
    #define INS2(da_, db_, s_) do { \
        if (fminf(da_, db_) < t2[s_]) { INS(da_, idx0, s_); INS(db_, idx0 + 1, s_); } } while (0)

    // ---- prologue copy (12 KB tile: 6 x cp.async.16 per thread)
    if (slab < nt) {
        const uint8_t* src = g_btiles + (size_t)slab * TBYTES;
        #pragma unroll
        for (int i = 0; i < 6; ++i) cpa16(smb + tid * 16 + i * 2048, src + tid * 16 + i * 2048);
    }
    CP_COMMIT();

    int it = 0;
    for (int t = slab; t < nt; t += SLABS, ++it) {
        CP_WAIT0();
        __syncthreads();
        const int buf = it & 1;
        const uint32_t bufb = smb + (uint32_t)buf * TBYTES;
        const int tn = t + SLABS;
        if (tn < nt) {
            const uint32_t dstb = smb + (uint32_t)(buf ^ 1) * TBYTES;
            const uint8_t* src = g_btiles + (size_t)tn * TBYTES;
            #pragma unroll
            for (int i = 0; i < 6; ++i) cpa16(dstb + tid * 16 + i * 2048, src + tid * 16 + i * 2048);
        }
        CP_COMMIT();

        const int tb = t * TILE;
        #pragma unroll 2
        for (int j = 0; j < 8; ++j) {
            const uint32_t bb = bufb + (uint32_t)(j * 8 + g) * RPITCH + c * 16;
            float d0,d1,d2,d3;
            uint32_t e0,e1,o0,o1;
            lds128(e0, e1, o0, o1, bb);                  // s0, s1
            MMA0(d0,d1,d2,d3, a0[0],a1[0],a2[0],a3[0], e0,e1);
            MMA (d0,d1,d2,d3, a0[1],a1[1],a2[1],a3[1], o0,o1);
            lds128(e0, e1, o0, o1, bb + 64);             // s2, s3
            MMA (d0,d1,d2,d3, a0[2],a1[2],a2[2],a3[2], e0,e1);
            MMA (d0,d1,d2,d3, a0[3],a1[3],a2[3],a3[3], o0,o1);
            lds128(e0, e1, o0, o1, bb + 128);            // s4, s5
            MMA (d0,d1,d2,d3, a0[4],a1[4],a2[4],a3[4], e0,e1);
            MMA (d0,d1,d2,d3, a0[5],a1[5],a2[5],a3[5], o0,o1);

            const int idx0 = tb + j * 8 + 2 * c;
            INS2(d0, d1, 0);     // row g
            INS2(d2, d3, 1);     // row g+8
        }
        __syncthreads();
    }
    #undef INS2
    #undef INS

    // ---- merge top-3 across the 4 lanes of each quad (same queries, disjoint cols)
    #pragma unroll
    for (int s = 0; s < 2; ++s) {
        #pragma unroll
        for (int off = 2; off > 0; off >>= 1) {
            float o0 = __shfl_down_sync(0xffffffffu, t0[s], off);
            float o1 = __shfl_down_sync(0xffffffffu, t1[s], off);
            float o2 = __shfl_down_sync(0xffffffffu, t2[s], off);
            int   z0 = __shfl_down_sync(0xffffffffu, i0[s], off);
            int   z1 = __shfl_down_sync(0xffffffffu, i1[s], off);
            int   z2 = __shfl_down_sync(0xffffffffu, i2[s], off);
            #define MINS(vv, zz) do { \
                float _v = (vv); int _z = (zz); \
                if (_v < t2[s] || (_v == t2[s] && _z < i2[s])) { \
                    if (_v < t1[s] || (_v == t1[s] && _z < i1[s])) { \
                        t2[s]=t1[s]; i2[s]=i1[s]; \
                        if (_v < t0[s] || (_v == t0[s] && _z < i0[s])) { t1[s]=t0[s]; i1[s]=i0[s]; t0[s]=_v; i0[s]=_z; } \
                        else { t1[s]=_v; i1[s]=_z; } \
                    } else { t2[s]=_v; i2[s]=_z; } \
                } } while (0)
            MINS(o0, z0); MINS(o1, z1); MINS(o2, z2);
            #undef MINS
        }
    }
    if ((lane & 3) == 0) {
        #pragma unroll
        for (int s = 0; s < 2; ++s) {
            const int q = qbase + w * 16 + g + s * 8;
            float2* o = g_part + ((size_t)q * SLABS + slab) * KNN;
            o[0] = make_float2(t0[s], __int_as_float(i0[s]));
            o[1] = make_float2(t1[s], __int_as_float(i1[s]));
            o[2] = make_float2(t2[s], __int_as_float(i2[s]));
        }
    }
}

// ---------------- merge + vote -------------------------------------------------
__device__ __forceinline__ void ins3(float v, int ix,
                                     float& r0, int& y0, float& r1, int& y1,
                                     float& r2, int& y2) {
    if (v < r2 || (v == r2 && ix < y2)) {
        if (v < r1 || (v == r1 && ix < y1)) {
            r2 = r1; y2 = y1;
            if (v < r0 || (v == r0 && ix < y0)) { r1 = r0; y1 = y0; r0 = v; y0 = ix; }
            else                                 { r1 = v;  y1 = ix; }
        } else { r2 = v; y2 = ix; }
    }
}

__global__ void k_reduce(const float* __restrict__ labels, float* __restrict__ out) {
    const int q    = blockIdx.x;
    const int tid  = threadIdx.x;   // 128
    const int lane = tid & 31;
    const int wid  = tid >> 5;
    __shared__ float sd[12];
    __shared__ int   si[12];
    const float INF = __int_as_float(0x7f800000);

    float b0 = INF, b1 = INF, b2 = INF;
    int   x0 = 0,   x1 = 0,   x2 = 0;
    const float2* p = g_part + (size_t)q * SLABS * KNN;
    for (int e = tid; e < SLABS * KNN; e += 128) {
        float2 v = p[e];
        ins3(v.x, __float_as_int(v.y), b0, x0, b1, x1, b2, x2);
    }
    #pragma unroll
    for (int off = 16; off > 0; off >>= 1) {
        float o0 = __shfl_down_sync(0xffffffffu, b0, off);
        float o1 = __shfl_down_sync(0xffffffffu, b1, off);
        float o2 = __shfl_down_sync(0xffffffffu, b2, off);
        int   z0 = __shfl_down_sync(0xffffffffu, x0, off);
        int   z1 = __shfl_down_sync(0xffffffffu, x1, off);
        int   z2 = __shfl_down_sync(0xffffffffu, x2, off);
        ins3(o0, z0, b0, x0, b1, x1, b2, x2);
        ins3(o1, z1, b0, x0, b1, x1, b2, x2);
        ins3(o2, z2, b0, x0, b1, x1, b2, x2);
    }
    if (lane == 0) {
        sd[wid * 3 + 0] = b0; si[wid * 3 + 0] = x0;
        sd[wid * 3 + 1] = b1; si[wid * 3 + 1] = x1;
        sd[wid * 3 + 2] = b2; si[wid * 3 + 2] = x2;
    }
    __syncthreads();

    if (tid == 0) {
        float r0 = sd[0], r1 = sd[1], r2 = sd[2];
        int   y0 = si[0], y1 = si[1], y2 = si[2];
        #pragma unroll
        for (int e = 3; e < 12; ++e) ins3(sd[e], si[e], r0, y0, r1, y1, r2, y2);

        const float qn = g_qn[q];
        const float kd0 = sqrtf(fmaxf(r0 + qn, 0.f));
        const float kd1 = sqrtf(fmaxf(r1 + qn, 0.f));
        const float kd2 = sqrtf(fmaxf(r2 + qn, 0.f));
        out[q * KNN + 0] = kd0;
        out[q * KNN + 1] = kd1;
        out[q * KNN + 2] = kd2;

        const float w0 = (kd0 == 0.f) ? 1.f : kd0;
        const float w1 = (kd1 == 0.f) ? 1.f : kd1;
        const float w2 = (kd2 == 0.f) ? 1.f : kd2;
        const float* l0 = labels + (size_t)y0 * NCLS;
        const float* l1 = labels + (size_t)y1 * NCLS;
        const float* l2 = labels + (size_t)y2 * NCLS;

        float votes[NCLS];
        #pragma unroll
        for (int cc = 0; cc < NCLS; ++cc)
            votes[cc] = l0[cc] / w0 + l1[cc] / w1 + l2[cc] / w2;

        int am = 0; float bm = votes[0];
        #pragma unroll
        for (int cc = 1; cc < NCLS; ++cc)
            if (votes[cc] > bm) { bm = votes[cc]; am = cc; }

        const bool zero_hit = (kd0 == 0.f);
        float* ro = out + QB * KNN + q * NCLS;
        #pragma unroll
        for (int cc = 0; cc < NCLS; ++cc)
            ro[cc] = zero_hit ? l0[cc] : ((cc == am) ? 1.f : 0.f);
    }
}

// ---------------- launch --------------------------------------------------------
extern "C" void kernel_launch(void* const* d_in, const int* in_sizes, int n_in,
                              void* d_out, int out_size) {
    const float* query = (const float*)d_in[0];
    const float* tf    = (const float*)d_in[1];
    const float* tl    = (const float*)d_in[2];
    float* out = (float*)d_out;
    const int n_elems = in_sizes[1];
    const int N = n_elems / D;
    const int nt = (N + TILE - 1) / TILE;
    const int NP = nt * TILE;

    k_init  <<<1,   32 >>>();
    k_scale <<<888, 216>>>(tf, n_elems);
    k_query <<<1,   QB >>>(query);
    k_prep  <<<(NP + 127) / 128, 128>>>(tf, N, NP);
    k_hmma  <<<SLABS * GROUPS, 128, SMEM_TOT>>>(N);
    k_reduce<<<QB,  128>>>(tl, out);
}

// round 10
// speedup vs baseline: 1.1431x; 1.1121x over previous
#include <cuda_runtime.h>
#include <cuda_bf16.h>
#include <stdint.h>
#include <math.h>

#define D        27
#define QB       512
#define NCLS     11
#define KNN      3
#define SLABS    148
#define GROUPS   8                    // query groups of 64
#define TILE     64
#define RPITCH   192                  // bytes per formatted row (3 k16-block pairs)
#define TBYTES   (TILE * RPITCH)      // 12288 per tile
#define NPMAX    409600
#define SMEM_TOT (2 * TBYTES + 128)

// ---------------- static device scratch ------------------------------------
__device__ unsigned int g_scale_bits[D];
__device__ float        g_qm[QB * D];     // -2 * scaled query
__device__ float        g_qn[QB];
__device__ float2       g_part[(size_t)QB * SLABS * KNN];
__device__ __align__(16) uint8_t g_btiles[(size_t)NPMAX * RPITCH];

// ---------------- helpers ----------------------------------------------------
__device__ __forceinline__ uint32_t smem_u32(const void* p) {
    uint32_t a;
    asm("{ .reg .u64 t; cvta.to.shared.u64 t, %1; cvt.u32.u64 %0, t; }" : "=r"(a) : "l"(p));
    return a;
}
__device__ __forceinline__ void lds128(uint32_t& x, uint32_t& y, uint32_t& z, uint32_t& w, uint32_t a) {
    asm volatile("ld.shared.v4.b32 {%0,%1,%2,%3}, [%4];"
                 : "=r"(x), "=r"(y), "=r"(z), "=r"(w) : "r"(a));
}
__device__ __forceinline__ void lds64(uint32_t& x, uint32_t& y, uint32_t a) {
    asm volatile("ld.shared.v2.b32 {%0,%1}, [%2];" : "=r"(x), "=r"(y) : "r"(a));
}
__device__ __forceinline__ void sts128(uint32_t a, uint32_t w0, uint32_t w1, uint32_t w2, uint32_t w3) {
    asm volatile("st.shared.v4.b32 [%0], {%1,%2,%3,%4};"
                 :: "r"(a), "r"(w0), "r"(w1), "r"(w2), "r"(w3) : "memory");
}
__device__ __forceinline__ void cpa16(uint32_t s, const void* g) {
    asm volatile("cp.async.cg.shared.global [%0], [%1], 16;" :: "r"(s), "l"(g) : "memory");
}
#define CP_COMMIT() asm volatile("cp.async.commit_group;" ::: "memory")
#define CP_WAIT0()  asm volatile("cp.async.wait_group 0;" ::: "memory")

__device__ __forceinline__ uint32_t pk(__nv_bfloat16 a, __nv_bfloat16 b) {
    unsigned short x = *(unsigned short*)&a, y = *(unsigned short*)&b;
    return (uint32_t)x | ((uint32_t)y << 16);
}

#define MMA(d0,d1,d2,d3, A0,A1,A2,A3, B0,B1) \
    asm volatile("mma.sync.aligned.m16n8k16.row.col.f32.bf16.bf16.f32 " \
        "{%0,%1,%2,%3}, {%4,%5,%6,%7}, {%8,%9}, {%0,%1,%2,%3};" \
        : "+f"(d0), "+f"(d1), "+f"(d2), "+f"(d3) \
        : "r"(A0), "r"(A1), "r"(A2), "r"(A3), "r"(B0), "r"(B1))

#define MMA0(d0,d1,d2,d3, A0,A1,A2,A3, B0,B1) \
    asm volatile("mma.sync.aligned.m16n8k16.row.col.f32.bf16.bf16.f32 " \
        "{%0,%1,%2,%3}, {%4,%5,%6,%7}, {%8,%9}, {%10,%11,%12,%13};" \
        : "=f"(d0), "=f"(d1), "=f"(d2), "=f"(d3) \
        : "r"(A0), "r"(A1), "r"(A2), "r"(A3), "r"(B0), "r"(B1), \
          "f"(0.f), "f"(0.f), "f"(0.f), "f"(0.f))

// ---------------- small kernels ----------------------------------------------
__global__ void k_init() { if (threadIdx.x < D) g_scale_bits[threadIdx.x] = 0u; }

__global__ void k_scale(const float* __restrict__ tf, int n) {
    __shared__ unsigned int sm[D];
    if (threadIdx.x < D) sm[threadIdx.x] = 0u;
    __syncthreads();
    int i = blockIdx.x * blockDim.x + threadIdx.x;
    int col = i % D;
    int stride = gridDim.x * blockDim.x;   // multiple of 27
    float m = 0.f;
    for (; i < n; i += stride) m = fmaxf(m, fabsf(tf[i]));
    atomicMax(&sm[col], __float_as_uint(m));
    __syncthreads();
    if (threadIdx.x < D) atomicMax(&g_scale_bits[threadIdx.x], sm[threadIdx.x]);
}

// ---------------- k_prep: format train set (and queries) ----------------------
// Train row layout (192 B): blocks s0=hi[0:16] s1=hi[16:27]+xnh@k27+xnl@k28
// s2=hi[0:16] s3=hi[16:27] s4=lo[0:16] s5=lo[16:27]; pair p at byte p*64;
// chunk c of a pair = {we[c], we[c+4], wo[c], wo[c+4]}.
// v3: float4-coalesced read -> linear stride-27 smem (conflict-free) -> register
// pack -> staged coalesced STG.128 stream (unioned smem buffer).
// Blocks 0-3 additionally format the 512 queries (g_qm, g_qn).
__global__ void __launch_bounds__(128) k_prep(const float* __restrict__ tf,
                                              const float* __restrict__ query,
                                              int N, int NP) {
    __shared__ __align__(16) char buf[128 * 12 * 16];   // 24576 B union
    __shared__ float inv[D];
    float* st  = (float*)buf;          // phase 1: 128*27 floats (13824 B)
    uint4* pkm = (uint4*)buf;          // phase 3: 128*12 uint4
    const int tid = threadIdx.x;
    const int p0  = blockIdx.x * 128;
    if (tid < D) {
        float s = __uint_as_float(g_scale_bits[tid]);
        inv[tid] = (s != 0.f) ? (1.f / s) : 0.f;   // divide_no_nan
    }
    __syncthreads();

    // ---- query side (blocks 0-3; 128 queries each)
    if (blockIdx.x < 4) {
        const int q = blockIdx.x * 128 + tid;
        float qn = 0.f;
        #pragma unroll
        for (int d = 0; d < D; ++d) {
            float v = query[q * D + d] * inv[d];
            qn = fmaf(v, v, qn);
            g_qm[q * D + d] = -2.f * v;
        }
        g_qn[q] = qn;
    }

    // ---- phase 1: coalesced read into linear smem
    if (p0 + 128 <= N) {
        const float4* src = (const float4*)(tf + (size_t)p0 * D);
        float4* dst4 = (float4*)st;
        #pragma unroll
        for (int k = 0; k < 7; ++k) {
            int i = tid + k * 128;
            if (i < 864) dst4[i] = src[i];
        }
    } else {
        const int lim = (N - p0) * D;
        for (int i = tid; i < 128 * D; i += 128)
            st[i] = (i < lim) ? tf[(size_t)p0 * D + i] : 0.f;
    }
    __syncthreads();

    // ---- phase 2: per-thread scale + split + pack (registers only)
    const int p = p0 + tid;
    float v[27];
    float xn = 0.f;
    #pragma unroll
    for (int d = 0; d < D; ++d) {
        float x = st[tid * D + d] * inv[d];   // stride 27 -> conflict-free
        v[d] = x;
        xn = fmaf(x, x, xn);
    }
    if (p >= N) xn = 1e30f;     // padding rows never win top-3

    __nv_bfloat16 hb[27], lb[27];
    #pragma unroll
    for (int d = 0; d < D; ++d) {
        hb[d] = __float2bfloat16(v[d]);
        lb[d] = __float2bfloat16(v[d] - __bfloat162float(hb[d]));
    }
    const __nv_bfloat16 zr = __float2bfloat16(0.f);
    __nv_bfloat16 xh = __float2bfloat16(xn);
    __nv_bfloat16 xl = __float2bfloat16(xn - __bfloat162float(xh));

    uint32_t hw0[8], lw0[8], s1b[8], s3b[8], s5b[8];
    #pragma unroll
    for (int j = 0; j < 8; ++j) {
        hw0[j] = pk(hb[2*j], hb[2*j+1]);
        lw0[j] = pk(lb[2*j], lb[2*j+1]);
    }
    #pragma unroll
    for (int j = 0; j < 5; ++j) {
        s1b[j] = pk(hb[16+2*j], hb[17+2*j]);
        s3b[j] = s1b[j];
        s5b[j] = pk(lb[16+2*j], lb[17+2*j]);
    }
    s1b[5] = pk(hb[26], xh); s1b[6] = pk(xl, zr); s1b[7] = 0;
    s3b[5] = pk(hb[26], zr); s3b[6] = 0;          s3b[7] = 0;
    s5b[5] = pk(lb[26], zr); s5b[6] = 0;          s5b[7] = 0;

    uint4 my[12];
    #pragma unroll
    for (int c = 0; c < 4; ++c) {
        my[c]     = make_uint4(hw0[c], hw0[c+4], s1b[c], s1b[c+4]);  // pair (s0,s1)
        my[4 + c] = make_uint4(hw0[c], hw0[c+4], s3b[c], s3b[c+4]);  // pair (s2,s3)
        my[8 + c] = make_uint4(lw0[c], lw0[c+4], s5b[c], s5b[c+4]);  // pair (s4,s5)
    }
    __syncthreads();   // all st reads done before pkm overwrites buf
    if (p < NP) {
        #pragma unroll
        for (int i = 0; i < 12; ++i) pkm[tid * 12 + i] = my[i];
    }
    __syncthreads();

    // ---- phase 3: coalesced STG.128 stream of the block's 24 KB
    const int npts = min(128, NP - p0);
    if (npts > 0) {
        uint4* gd = (uint4*)(g_btiles + (size_t)p0 * RPITCH);
        const int tot = npts * 12;
        for (int i = tid; i < tot; i += 128) gd[i] = pkm[i];
    }
}

// ---------------- main HMMA kernel: 1 m-tile/warp, 8 CTAs/SM, A-dedup ---------
__global__ void __launch_bounds__(128, 8)
k_hmma(int N) {
    extern __shared__ char smraw[];
    const uint32_t smb = smem_u32(smraw);
    const int tid  = threadIdx.x;
    const int w    = tid >> 5;
    const int lane = tid & 31;
    const int g    = lane >> 2;
    const int c    = lane & 3;
    const int qg   = blockIdx.x & 7;
    const int slab = blockIdx.x >> 3;
    const int qbase = qg * 64;
    const int nt = (N + TILE - 1) / TILE;

    // ---- stage A rows (64 queries, threads 0-63), 192B pair layout
    if (tid < 64) {
        const int q = qbase + tid;
        __nv_bfloat16 hi_[27], lo_[27];
        #pragma unroll
        for (int d = 0; d < D; ++d) {
            float v = g_qm[q * D + d];
            __nv_bfloat16 h = __float2bfloat16(v);
            hi_[d] = h;
            lo_[d] = __float2bfloat16(v - __bfloat162float(h));
        }
        const __nv_bfloat16 one = __float2bfloat16(1.f);
        const __nv_bfloat16 zr  = __float2bfloat16(0.f);
        uint32_t hw[8], lw[8], b1[8], b3[8], b5[8];
        #pragma unroll
        for (int j = 0; j < 8; ++j) {
            hw[j] = pk(hi_[2*j], hi_[2*j+1]);
            lw[j] = pk(lo_[2*j], lo_[2*j+1]);
        }
        #pragma unroll
        for (int j = 0; j < 5; ++j) {
            b1[j] = pk(hi_[16+2*j], hi_[17+2*j]);
            b5[j] = b1[j];
            b3[j] = pk(lo_[16+2*j], lo_[17+2*j]);
        }
        b1[5] = pk(hi_[26], one); b1[6] = pk(one, zr); b1[7] = 0;  // ones pick up xn
        b3[5] = pk(lo_[26], zr);  b3[6] = 0;           b3[7] = 0;
        b5[5] = pk(hi_[26], zr);  b5[6] = 0;           b5[7] = 0;
        const uint32_t rowa = smb + tid * RPITCH;
        #pragma unroll
        for (int cc = 0; cc < 4; ++cc) {
            sts128(rowa +       cc*16, hw[cc], hw[cc+4], b1[cc], b1[cc+4]); // (s0,s1)
            sts128(rowa +  64 + cc*16, lw[cc], lw[cc+4], b3[cc], b3[cc+4]); // (s2,s3)
            sts128(rowa + 128 + cc*16, hw[cc], hw[cc+4], b5[cc], b5[cc+4]); // (s4,s5)
        }
    }
    __syncthreads();

    // ---- persistent A fragments: 5 unique sets (s4 == s0)
    // set idx: 0=s0(hi_e) 1=s1(hi_o+ones) 2=s2(lo_e) 3=s3(lo_o) 4=s5(hi_o+zeros)
    uint32_t A0[5], A1[5], A2[5], A3[5];
    {
        const uint32_t base = smb + (uint32_t)(w * 16 + g) * RPITCH + c * 16;
        lds128(A0[0], A2[0], A0[1], A2[1], base);
        lds128(A1[0], A3[0], A1[1], A3[1], base + 8 * RPITCH);
        lds128(A0[2], A2[2], A0[3], A2[3], base + 64);
        lds128(A1[2], A3[2], A1[3], A3[3], base + 64 + 8 * RPITCH);
        lds64 (A0[4], A2[4], base + 128 + 8);                    // s5 odd half, row g
        lds64 (A1[4], A3[4], base + 128 + 8 + 8 * RPITCH);       // s5 odd half, row g+8
    }
    __syncthreads();

    const float INF = __int_as_float(0x7f800000);
    float t0[2], t1[2], t2[2];
    int   i0[2], i1[2], i2[2];
    #pragma unroll
    for (int s = 0; s < 2; ++s) { t0[s]=t1[s]=t2[s]=INF; i0[s]=i1[s]=i2[s]=0; }

    #define INS(v_, idx_, s_) do { \
        float _v = (v_); \
        if (_v < t2[s_]) { \
            int _ix = (idx_); \
            if (_v < t1[s_]) { \
                t2[s_] = t1[s_]; i2[s_] = i1[s_]; \
                if (_v < t0[s_]) { t1[s_]=t0[s_]; i1[s_]=i0[s_]; t0[s_]=_v; i0[s_]=_ix; } \
                else             { t1[s_]=_v; i1[s_]=_ix; } \
            } else { t2[s_] = _v; i2[s_] = _ix; } \
        } } while (0)
    #define INS2(da_, db_, s_) do { \
        if (fminf(da_, db_) < t2[s_]) { INS(da_, idx0, s_); INS(db_, idx0 + 1, s_); } } while (0)

    // ---- prologue copy (12 KB tile: 6 x cp.async.16 per thread)
    if (slab < nt) {
        const uint8_t* src = g_btiles + (size_t)slab * TBYTES;
        #pragma unroll
        for (int i = 0; i < 6; ++i) cpa16(smb + tid * 16 + i * 2048, src + tid * 16 + i * 2048);
    }
    CP_COMMIT();

    int it = 0;
    for (int t = slab; t < nt; t += SLABS, ++it) {
        CP_WAIT0();
        __syncthreads();
        const int buf = it & 1;
        const uint32_t bufb = smb + (uint32_t)buf * TBYTES;
        const int tn = t + SLABS;
        if (tn < nt) {
            const uint32_t dstb = smb + (uint32_t)(buf ^ 1) * TBYTES;
            const uint8_t* src = g_btiles + (size_t)tn * TBYTES;
            #pragma unroll
            for (int i = 0; i < 6; ++i) cpa16(dstb + tid * 16 + i * 2048, src + tid * 16 + i * 2048);
        }
        CP_COMMIT();

        const int tb = t * TILE;
        #pragma unroll 2
        for (int j = 0; j < 8; ++j) {
            const uint32_t bb = bufb + (uint32_t)(j * 8 + g) * RPITCH + c * 16;
            float d0,d1,d2,d3;
            uint32_t e0,e1,o0,o1;
            lds128(e0, e1, o0, o1, bb);                  // B s0, s1
            MMA0(d0,d1,d2,d3, A0[0],A1[0],A2[0],A3[0], e0,e1);
            MMA (d0,d1,d2,d3, A0[1],A1[1],A2[1],A3[1], o0,o1);
            lds128(e0, e1, o0, o1, bb + 64);             // B s2, s3
            MMA (d0,d1,d2,d3, A0[2],A1[2],A2[2],A3[2], e0,e1);
            MMA (d0,d1,d2,d3, A0[3],A1[3],A2[3],A3[3], o0,o1);
            lds128(e0, e1, o0, o1, bb + 128);            // B s4, s5
            MMA (d0,d1,d2,d3, A0[0],A1[0],A2[0],A3[0], e0,e1);   // A s4 == s0
            MMA (d0,d1,d2,d3, A0[4],A1[4],A2[4],A3[4], o0,o1);

            const int idx0 = tb + j * 8 + 2 * c;
            INS2(d0, d1, 0);     // row g
            INS2(d2, d3, 1);     // row g+8
        }
        __syncthreads();
    }
    #undef INS2
    #undef INS

    // ---- merge top-3 across the 4 lanes of each quad (same queries, disjoint cols)
    #pragma unroll
    for (int s = 0; s < 2; ++s) {
        #pragma unroll
        for (int off = 2; off > 0; off >>= 1) {
            float o0 = __shfl_down_sync(0xffffffffu, t0[s], off);
            float o1 = __shfl_down_sync(0xffffffffu, t1[s], off);
            float o2 = __shfl_down_sync(0xffffffffu, t2[s], off);
            int   z0 = __shfl_down_sync(0xffffffffu, i0[s], off);
            int   z1 = __shfl_down_sync(0xffffffffu, i1[s], off);
            int   z2 = __shfl_down_sync(0xffffffffu, i2[s], off);
            #define MINS(vv, zz) do { \
                float _v = (vv); int _z = (zz); \
                if (_v < t2[s] || (_v == t2[s] && _z < i2[s])) { \
                    if (_v < t1[s] || (_v == t1[s] && _z < i1[s])) { \
                        t2[s]=t1[s]; i2[s]=i1[s]; \
                        if (_v < t0[s] || (_v == t0[s] && _z < i0[s])) { t1[s]=t0[s]; i1[s]=i0[s]; t0[s]=_v; i0[s]=_z; } \
                        else { t1[s]=_v; i1[s]=_z; } \
                    } else { t2[s]=_v; i2[s]=_z; } \
                } } while (0)
            MINS(o0, z0); MINS(o1, z1); MINS(o2, z2);
            #undef MINS
        }
    }
    if ((lane & 3) == 0) {
        #pragma unroll
        for (int s = 0; s < 2; ++s) {
            const int q = qbase + w * 16 + g + s * 8;
            float2* o = g_part + ((size_t)q * SLABS + slab) * KNN;
            o[0] = make_float2(t0[s], __int_as_float(i0[s]));
            o[1] = make_float2(t1[s], __int_as_float(i1[s]));
            o[2] = make_float2(t2[s], __int_as_float(i2[s]));
        }
    }
}

// ---------------- merge + vote -------------------------------------------------
__device__ __forceinline__ void ins3(float v, int ix,
                                     float& r0, int& y0, float& r1, int& y1,
                                     float& r2, int& y2) {
    if (v < r2 || (v == r2 && ix < y2)) {
        if (v < r1 || (v == r1 && ix < y1)) {
            r2 = r1; y2 = y1;
            if (v < r0 || (v == r0 && ix < y0)) { r1 = r0; y1 = y0; r0 = v; y0 = ix; }
            else                                 { r1 = v;  y1 = ix; }
        } else { r2 = v; y2 = ix; }
    }
}

__global__ void k_reduce(const float* __restrict__ labels, float* __restrict__ out) {
    const int q    = blockIdx.x;
    const int tid  = threadIdx.x;   // 128
    const int lane = tid & 31;
    const int wid  = tid >> 5;
    __shared__ float sd[12];
    __shared__ int   si[12];
    const float INF = __int_as_float(0x7f800000);

    float b0 = INF, b1 = INF, b2 = INF;
    int   x0 = 0,   x1 = 0,   x2 = 0;
    const float2* p = g_part + (size_t)q * SLABS * KNN;
    for (int e = tid; e < SLABS * KNN; e += 128) {
        float2 v = p[e];
        ins3(v.x, __float_as_int(v.y), b0, x0, b1, x1, b2, x2);
    }
    #pragma unroll
    for (int off = 16; off > 0; off >>= 1) {
        float o0 = __shfl_down_sync(0xffffffffu, b0, off);
        float o1 = __shfl_down_sync(0xffffffffu, b1, off);
        float o2 = __shfl_down_sync(0xffffffffu, b2, off);
        int   z0 = __shfl_down_sync(0xffffffffu, x0, off);
        int   z1 = __shfl_down_sync(0xffffffffu, x1, off);
        int   z2 = __shfl_down_sync(0xffffffffu, x2, off);
        ins3(o0, z0, b0, x0, b1, x1, b2, x2);
        ins3(o1, z1, b0, x0, b1, x1, b2, x2);
        ins3(o2, z2, b0, x0, b1, x1, b2, x2);
    }
    if (lane == 0) {
        sd[wid * 3 + 0] = b0; si[wid * 3 + 0] = x0;
        sd[wid * 3 + 1] = b1; si[wid * 3 + 1] = x1;
        sd[wid * 3 + 2] = b2; si[wid * 3 + 2] = x2;
    }
    __syncthreads();

    if (tid == 0) {
        float r0 = sd[0], r1 = sd[1], r2 = sd[2];
        int   y0 = si[0], y1 = si[1], y2 = si[2];
        #pragma unroll
        for (int e = 3; e < 12; ++e) ins3(sd[e], si[e], r0, y0, r1, y1, r2, y2);

        const float qn = g_qn[q];
        const float kd0 = sqrtf(fmaxf(r0 + qn, 0.f));
        const float kd1 = sqrtf(fmaxf(r1 + qn, 0.f));
        const float kd2 = sqrtf(fmaxf(r2 + qn, 0.f));
        out[q * KNN + 0] = kd0;
        out[q * KNN + 1] = kd1;
        out[q * KNN + 2] = kd2;

        const float w0 = (kd0 == 0.f) ? 1.f : kd0;
        const float w1 = (kd1 == 0.f) ? 1.f : kd1;
        const float w2 = (kd2 == 0.f) ? 1.f : kd2;
        const float* l0 = labels + (size_t)y0 * NCLS;
        const float* l1 = labels + (size_t)y1 * NCLS;
        const float* l2 = labels + (size_t)y2 * NCLS;

        float votes[NCLS];
        #pragma unroll
        for (int cc = 0; cc < NCLS; ++cc)
            votes[cc] = l0[cc] / w0 + l1[cc] / w1 + l2[cc] / w2;

        int am = 0; float bm = votes[0];
        #pragma unroll
        for (int cc = 1; cc < NCLS; ++cc)
            if (votes[cc] > bm) { bm = votes[cc]; am = cc; }

        const bool zero_hit = (kd0 == 0.f);
        float* ro = out + QB * KNN + q * NCLS;
        #pragma unroll
        for (int cc = 0; cc < NCLS; ++cc)
            ro[cc] = zero_hit ? l0[cc] : ((cc == am) ? 1.f : 0.f);
    }
}

// ---------------- launch --------------------------------------------------------
extern "C" void kernel_launch(void* const* d_in, const int* in_sizes, int n_in,
                              void* d_out, int out_size) {
    const float* query = (const float*)d_in[0];
    const float* tf    = (const float*)d_in[1];
    const float* tl    = (const float*)d_in[2];
    float* out = (float*)d_out;
    const int n_elems = in_sizes[1];
    const int N = n_elems / D;
    const int nt = (N + TILE - 1) / TILE;
    const int NP = nt * TILE;

    k_init  <<<1,   32 >>>();
    k_scale <<<888, 216>>>(tf, n_elems);
    k_prep  <<<(NP + 127) / 128, 128>>>(tf, query, N, NP);
    k_hmma  <<<SLABS * GROUPS, 128, SMEM_TOT>>>(N);
    k_reduce<<<QB,  128>>>(tl, out);
}

// round 11
// speedup vs baseline: 1.1477x; 1.0041x over previous
#include <cuda_runtime.h>
#include <cuda_bf16.h>
#include <stdint.h>
#include <math.h>

#define D        27
#define QB       512
#define NCLS     11
#define KNN      3
#define SLABS    148
#define GROUPS   8                    // query groups of 64
#define TILE     64
#define RPITCH   192                  // bytes per formatted row (3 k16-block pairs)
#define TBYTES   (TILE * RPITCH)      // 12288 per tile
#define NPMAX    409600
#define SMEM_TOT (2 * TBYTES + 128)

// ---------------- static device scratch ------------------------------------
__device__ unsigned int g_scale_bits[D];
__device__ float        g_qm[QB * D];     // -2 * scaled query
__device__ float        g_qn[QB];
__device__ float2       g_part[(size_t)QB * SLABS * KNN];
__device__ __align__(16) uint8_t g_btiles[(size_t)NPMAX * RPITCH];

// ---------------- helpers ----------------------------------------------------
__device__ __forceinline__ uint32_t smem_u32(const void* p) {
    uint32_t a;
    asm("{ .reg .u64 t; cvta.to.shared.u64 t, %1; cvt.u32.u64 %0, t; }" : "=r"(a) : "l"(p));
    return a;
}
__device__ __forceinline__ void lds128(uint32_t& x, uint32_t& y, uint32_t& z, uint32_t& w, uint32_t a) {
    asm volatile("ld.shared.v4.b32 {%0,%1,%2,%3}, [%4];"
                 : "=r"(x), "=r"(y), "=r"(z), "=r"(w) : "r"(a));
}
__device__ __forceinline__ void lds64(uint32_t& x, uint32_t& y, uint32_t a) {
    asm volatile("ld.shared.v2.b32 {%0,%1}, [%2];" : "=r"(x), "=r"(y) : "r"(a));
}
__device__ __forceinline__ void sts128(uint32_t a, uint32_t w0, uint32_t w1, uint32_t w2, uint32_t w3) {
    asm volatile("st.shared.v4.b32 [%0], {%1,%2,%3,%4};"
                 :: "r"(a), "r"(w0), "r"(w1), "r"(w2), "r"(w3) : "memory");
}
__device__ __forceinline__ void cpa16(uint32_t s, const void* g) {
    asm volatile("cp.async.cg.shared.global [%0], [%1], 16;" :: "r"(s), "l"(g) : "memory");
}
#define CP_COMMIT() asm volatile("cp.async.commit_group;" ::: "memory")
#define CP_WAIT0()  asm volatile("cp.async.wait_group 0;" ::: "memory")

__device__ __forceinline__ uint32_t pk(__nv_bfloat16 a, __nv_bfloat16 b) {
    unsigned short x = *(unsigned short*)&a, y = *(unsigned short*)&b;
    return (uint32_t)x | ((uint32_t)y << 16);
}

#define MMA(d0,d1,d2,d3, A0,A1,A2,A3, B0,B1) \
    asm volatile("mma.sync.aligned.m16n8k16.row.col.f32.bf16.bf16.f32 " \
        "{%0,%1,%2,%3}, {%4,%5,%6,%7}, {%8,%9}, {%0,%1,%2,%3};" \
        : "+f"(d0), "+f"(d1), "+f"(d2), "+f"(d3) \
        : "r"(A0), "r"(A1), "r"(A2), "r"(A3), "r"(B0), "r"(B1))

#define MMA0(d0,d1,d2,d3, A0,A1,A2,A3, B0,B1) \
    asm volatile("mma.sync.aligned.m16n8k16.row.col.f32.bf16.bf16.f32 " \
        "{%0,%1,%2,%3}, {%4,%5,%6,%7}, {%8,%9}, {%10,%11,%12,%13};" \
        : "=f"(d0), "=f"(d1), "=f"(d2), "=f"(d3) \
        : "r"(A0), "r"(A1), "r"(A2), "r"(A3), "r"(B0), "r"(B1), \
          "f"(0.f), "f"(0.f), "f"(0.f), "f"(0.f))

// ---------------- small kernels ----------------------------------------------
__global__ void k_init() { if (threadIdx.x < D) g_scale_bits[threadIdx.x] = 0u; }

__global__ void k_scale(const float* __restrict__ tf, int n) {
    __shared__ unsigned int sm[D];
    if (threadIdx.x < D) sm[threadIdx.x] = 0u;
    __syncthreads();
    int i = blockIdx.x * blockDim.x + threadIdx.x;
    int col = i % D;
    int stride = gridDim.x * blockDim.x;   // multiple of 27
    float m = 0.f;
    for (; i < n; i += stride) m = fmaxf(m, fabsf(tf[i]));
    atomicMax(&sm[col], __float_as_uint(m));
    __syncthreads();
    if (threadIdx.x < D) atomicMax(&g_scale_bits[threadIdx.x], sm[threadIdx.x]);
}

// ---------------- k_prep: format train set (and queries) ----------------------
// Train row layout (192 B): blocks s0=hi[0:16] s1=hi[16:27]+xnh@k27+xnl@k28
// s2=hi[0:16] s3=hi[16:27] s4=lo[0:16] s5=lo[16:27]; pair p at byte p*64;
// chunk c of a pair = {we[c], we[c+4], wo[c], wo[c+4]}.
__global__ void __launch_bounds__(128) k_prep(const float* __restrict__ tf,
                                              const float* __restrict__ query,
                                              int N, int NP) {
    __shared__ __align__(16) char buf[128 * 12 * 16];   // 24576 B union
    __shared__ float inv[D];
    float* st  = (float*)buf;          // phase 1: 128*27 floats (13824 B)
    uint4* pkm = (uint4*)buf;          // phase 3: 128*12 uint4
    const int tid = threadIdx.x;
    const int p0  = blockIdx.x * 128;
    if (tid < D) {
        float s = __uint_as_float(g_scale_bits[tid]);
        inv[tid] = (s != 0.f) ? (1.f / s) : 0.f;   // divide_no_nan
    }
    __syncthreads();

    // ---- query side (blocks 0-3; 128 queries each)
    if (blockIdx.x < 4) {
        const int q = blockIdx.x * 128 + tid;
        float qn = 0.f;
        #pragma unroll
        for (int d = 0; d < D; ++d) {
            float v = query[q * D + d] * inv[d];
            qn = fmaf(v, v, qn);
            g_qm[q * D + d] = -2.f * v;
        }
        g_qn[q] = qn;
    }

    // ---- phase 1: coalesced read into linear smem
    if (p0 + 128 <= N) {
        const float4* src = (const float4*)(tf + (size_t)p0 * D);
        float4* dst4 = (float4*)st;
        #pragma unroll
        for (int k = 0; k < 7; ++k) {
            int i = tid + k * 128;
            if (i < 864) dst4[i] = src[i];
        }
    } else {
        const int lim = (N - p0) * D;
        for (int i = tid; i < 128 * D; i += 128)
            st[i] = (i < lim) ? tf[(size_t)p0 * D + i] : 0.f;
    }
    __syncthreads();

    // ---- phase 2: per-thread scale + split + pack (registers only)
    const int p = p0 + tid;
    float v[27];
    float xn = 0.f;
    #pragma unroll
    for (int d = 0; d < D; ++d) {
        float x = st[tid * D + d] * inv[d];   // stride 27 -> conflict-free
        v[d] = x;
        xn = fmaf(x, x, xn);
    }
    if (p >= N) xn = 1e30f;     // padding rows never win top-3

    __nv_bfloat16 hb[27], lb[27];
    #pragma unroll
    for (int d = 0; d < D; ++d) {
        hb[d] = __float2bfloat16(v[d]);
        lb[d] = __float2bfloat16(v[d] - __bfloat162float(hb[d]));
    }
    const __nv_bfloat16 zr = __float2bfloat16(0.f);
    __nv_bfloat16 xh = __float2bfloat16(xn);
    __nv_bfloat16 xl = __float2bfloat16(xn - __bfloat162float(xh));

    uint32_t hw0[8], lw0[8], s1b[8], s3b[8], s5b[8];
    #pragma unroll
    for (int j = 0; j < 8; ++j) {
        hw0[j] = pk(hb[2*j], hb[2*j+1]);
        lw0[j] = pk(lb[2*j], lb[2*j+1]);
    }
    #pragma unroll
    for (int j = 0; j < 5; ++j) {
        s1b[j] = pk(hb[16+2*j], hb[17+2*j]);
        s3b[j] = s1b[j];
        s5b[j] = pk(lb[16+2*j], lb[17+2*j]);
    }
    s1b[5] = pk(hb[26], xh); s1b[6] = pk(xl, zr); s1b[7] = 0;
    s3b[5] = pk(hb[26], zr); s3b[6] = 0;          s3b[7] = 0;
    s5b[5] = pk(lb[26], zr); s5b[6] = 0;          s5b[7] = 0;

    uint4 my[12];
    #pragma unroll
    for (int c = 0; c < 4; ++c) {
        my[c]     = make_uint4(hw0[c], hw0[c+4], s1b[c], s1b[c+4]);  // pair (s0,s1)
        my[4 + c] = make_uint4(hw0[c], hw0[c+4], s3b[c], s3b[c+4]);  // pair (s2,s3)
        my[8 + c] = make_uint4(lw0[c], lw0[c+4], s5b[c], s5b[c+4]);  // pair (s4,s5)
    }
    __syncthreads();   // all st reads done before pkm overwrites buf
    if (p < NP) {
        #pragma unroll
        for (int i = 0; i < 12; ++i) pkm[tid * 12 + i] = my[i];
    }
    __syncthreads();

    // ---- phase 3: coalesced STG.128 stream of the block's 24 KB
    const int npts = min(128, NP - p0);
    if (npts > 0) {
        uint4* gd = (uint4*)(g_btiles + (size_t)p0 * RPITCH);
        const int tot = npts * 12;
        for (int i = tid; i < tot; i += 128) gd[i] = pkm[i];
    }
}

// ---------------- main HMMA kernel: 1 m-tile/warp, 8 CTAs/SM, A-dedup ---------
__global__ void __launch_bounds__(128, 8)
k_hmma(int N) {
    extern __shared__ char smraw[];
    const uint32_t smb = smem_u32(smraw);
    const int tid  = threadIdx.x;
    const int w    = tid >> 5;
    const int lane = tid & 31;
    const int g    = lane >> 2;
    const int c    = lane & 3;
    const int qg   = blockIdx.x & 7;
    const int slab = blockIdx.x >> 3;
    const int qbase = qg * 64;
    const int nt = (N + TILE - 1) / TILE;

    // ---- stage A rows (64 queries, threads 0-63), 192B pair layout
    if (tid < 64) {
        const int q = qbase + tid;
        __nv_bfloat16 hi_[27], lo_[27];
        #pragma unroll
        for (int d = 0; d < D; ++d) {
            float v = g_qm[q * D + d];
            __nv_bfloat16 h = __float2bfloat16(v);
            hi_[d] = h;
            lo_[d] = __float2bfloat16(v - __bfloat162float(h));
        }
        const __nv_bfloat16 one = __float2bfloat16(1.f);
        const __nv_bfloat16 zr  = __float2bfloat16(0.f);
        uint32_t hw[8], lw[8], b1[8], b3[8], b5[8];
        #pragma unroll
        for (int j = 0; j < 8; ++j) {
            hw[j] = pk(hi_[2*j], hi_[2*j+1]);
            lw[j] = pk(lo_[2*j], lo_[2*j+1]);
        }
        #pragma unroll
        for (int j = 0; j < 5; ++j) {
            b1[j] = pk(hi_[16+2*j], hi_[17+2*j]);
            b5[j] = b1[j];
            b3[j] = pk(lo_[16+2*j], lo_[17+2*j]);
        }
        b1[5] = pk(hi_[26], one); b1[6] = pk(one, zr); b1[7] = 0;  // ones pick up xn
        b3[5] = pk(lo_[26], zr);  b3[6] = 0;           b3[7] = 0;
        b5[5] = pk(hi_[26], zr);  b5[6] = 0;           b5[7] = 0;
        const uint32_t rowa = smb + tid * RPITCH;
        #pragma unroll
        for (int cc = 0; cc < 4; ++cc) {
            sts128(rowa +       cc*16, hw[cc], hw[cc+4], b1[cc], b1[cc+4]); // (s0,s1)
            sts128(rowa +  64 + cc*16, lw[cc], lw[cc+4], b3[cc], b3[cc+4]); // (s2,s3)
            sts128(rowa + 128 + cc*16, hw[cc], hw[cc+4], b5[cc], b5[cc+4]); // (s4,s5)
        }
    }
    __syncthreads();

    // ---- persistent A fragments: 5 unique sets (s4 == s0)
    uint32_t A0[5], A1[5], A2[5], A3[5];
    {
        const uint32_t base = smb + (uint32_t)(w * 16 + g) * RPITCH + c * 16;
        lds128(A0[0], A2[0], A0[1], A2[1], base);
        lds128(A1[0], A3[0], A1[1], A3[1], base + 8 * RPITCH);
        lds128(A0[2], A2[2], A0[3], A2[3], base + 64);
        lds128(A1[2], A3[2], A1[3], A3[3], base + 64 + 8 * RPITCH);
        lds64 (A0[4], A2[4], base + 128 + 8);
        lds64 (A1[4], A3[4], base + 128 + 8 + 8 * RPITCH);
    }
    __syncthreads();

    const float INF = __int_as_float(0x7f800000);
    float t0[2], t1[2], t2[2];
    int   i0[2], i1[2], i2[2];
    #pragma unroll
    for (int s = 0; s < 2; ++s) { t0[s]=t1[s]=t2[s]=INF; i0[s]=i1[s]=i2[s]=0; }

    #define INS(v_, idx_, s_) do { \
        float _v = (v_); \
        if (_v < t2[s_]) { \
            int _ix = (idx_); \
            if (_v < t1[s_]) { \
                t2[s_] = t1[s_]; i2[s_] = i1[s_]; \
                if (_v < t0[s_]) { t1[s_]=t0[s_]; i1[s_]=i0[s_]; t0[s_]=_v; i0[s_]=_ix; } \
                else             { t1[s_]=_v; i1[s_]=_ix; } \
            } else { t2[s_] = _v; i2[s_] = _ix; } \
        } } while (0)
    #define INS2(da_, db_, s_) do { \
        if (fminf(da_, db_) < t2[s_]) { INS(da_, idx0, s_); INS(db_, idx0 + 1, s_); } } while (0)

    // ---- prologue copy (12 KB tile: 6 x cp.async.16 per thread)
    if (slab < nt) {
        const uint8_t* src = g_btiles + (size_t)slab * TBYTES;
        #pragma unroll
        for (int i = 0; i < 6; ++i) cpa16(smb + tid * 16 + i * 2048, src + tid * 16 + i * 2048);
    }
    CP_COMMIT();

    int it = 0;
    for (int t = slab; t < nt; t += SLABS, ++it) {
        CP_WAIT0();
        __syncthreads();   // sole barrier: own copies done + all warps past prior tile
        const int buf = it & 1;
        const uint32_t bufb = smb + (uint32_t)buf * TBYTES;
        const int tn = t + SLABS;
        if (tn < nt) {
            const uint32_t dstb = smb + (uint32_t)(buf ^ 1) * TBYTES;
            const uint8_t* src = g_btiles + (size_t)tn * TBYTES;
            #pragma unroll
            for (int i = 0; i < 6; ++i) cpa16(dstb + tid * 16 + i * 2048, src + tid * 16 + i * 2048);
        }
        CP_COMMIT();

        uint32_t bb = bufb + (uint32_t)g * RPITCH + c * 16;
        int idx0 = t * TILE + 2 * c;
        #pragma unroll 4
        for (int j = 0; j < 8; ++j) {
            float d0,d1,d2,d3;
            uint32_t e0,e1,o0,o1;
            lds128(e0, e1, o0, o1, bb);                  // B s0, s1
            MMA0(d0,d1,d2,d3, A0[0],A1[0],A2[0],A3[0], e0,e1);
            MMA (d0,d1,d2,d3, A0[1],A1[1],A2[1],A3[1], o0,o1);
            lds128(e0, e1, o0, o1, bb + 64);             // B s2, s3
            MMA (d0,d1,d2,d3, A0[2],A1[2],A2[2],A3[2], e0,e1);
            MMA (d0,d1,d2,d3, A0[3],A1[3],A2[3],A3[3], o0,o1);
            lds128(e0, e1, o0, o1, bb + 128);            // B s4, s5
            MMA (d0,d1,d2,d3, A0[0],A1[0],A2[0],A3[0], e0,e1);   // A s4 == s0
            MMA (d0,d1,d2,d3, A0[4],A1[4],A2[4],A3[4], o0,o1);

            INS2(d0, d1, 0);     // row g
            INS2(d2, d3, 1);     // row g+8
            bb   += 8 * RPITCH;
            idx0 += 8;
        }
        // no end-of-tile barrier: next iteration's top barrier orders buffer reuse
    }
    #undef INS2
    #undef INS

    // ---- merge top-3 across the 4 lanes of each quad (same queries, disjoint cols)
    #pragma unroll
    for (int s = 0; s < 2; ++s) {
        #pragma unroll
        for (int off = 2; off > 0; off >>= 1) {
            float o0 = __shfl_down_sync(0xffffffffu, t0[s], off);
            float o1 = __shfl_down_sync(0xffffffffu, t1[s], off);
            float o2 = __shfl_down_sync(0xffffffffu, t2[s], off);
            int   z0 = __shfl_down_sync(0xffffffffu, i0[s], off);
            int   z1 = __shfl_down_sync(0xffffffffu, i1[s], off);
            int   z2 = __shfl_down_sync(0xffffffffu, i2[s], off);
            #define MINS(vv, zz) do { \
                float _v = (vv); int _z = (zz); \
                if (_v < t2[s] || (_v == t2[s] && _z < i2[s])) { \
                    if (_v < t1[s] || (_v == t1[s] && _z < i1[s])) { \
                        t2[s]=t1[s]; i2[s]=i1[s]; \
                        if (_v < t0[s] || (_v == t0[s] && _z < i0[s])) { t1[s]=t0[s]; i1[s]=i0[s]; t0[s]=_v; i0[s]=_z; } \
                        else { t1[s]=_v; i1[s]=_z; } \
                    } else { t2[s]=_v; i2[s]=_z; } \
                } } while (0)
            MINS(o0, z0); MINS(o1, z1); MINS(o2, z2);
            #undef MINS
        }
    }
    if ((lane & 3) == 0) {
        #pragma unroll
        for (int s = 0; s < 2; ++s) {
            const int q = qbase + w * 16 + g + s * 8;
            float2* o = g_part + ((size_t)q * SLABS + slab) * KNN;
            o[0] = make_float2(t0[s], __int_as_float(i0[s]));
            o[1] = make_float2(t1[s], __int_as_float(i1[s]));
            o[2] = make_float2(t2[s], __int_as_float(i2[s]));
        }
    }
}

// ---------------- merge + vote -------------------------------------------------
__device__ __forceinline__ void ins3(float v, int ix,
                                     float& r0, int& y0, float& r1, int& y1,
                                     float& r2, int& y2) {
    if (v < r2 || (v == r2 && ix < y2)) {
        if (v < r1 || (v == r1 && ix < y1)) {
            r2 = r1; y2 = y1;
            if (v < r0 || (v == r0 && ix < y0)) { r1 = r0; y1 = y0; r0 = v; y0 = ix; }
            else                                 { r1 = v;  y1 = ix; }
        } else { r2 = v; y2 = ix; }
    }
}

__global__ void k_reduce(const float* __restrict__ labels, float* __restrict__ out) {
    const int q    = blockIdx.x;
    const int tid  = threadIdx.x;   // 128
    const int lane = tid & 31;
    const int wid  = tid >> 5;
    __shared__ float sd[12];
    __shared__ int   si[12];
    const float INF = __int_as_float(0x7f800000);

    float b0 = INF, b1 = INF, b2 = INF;
    int   x0 = 0,   x1 = 0,   x2 = 0;
    const float2* p = g_part + (size_t)q * SLABS * KNN;
    for (int e = tid; e < SLABS * KNN; e += 128) {
        float2 v = p[e];
        ins3(v.x, __float_as_int(v.y), b0, x0, b1, x1, b2, x2);
    }
    #pragma unroll
    for (int off = 16; off > 0; off >>= 1) {
        float o0 = __shfl_down_sync(0xffffffffu, b0, off);
        float o1 = __shfl_down_sync(0xffffffffu, b1, off);
        float o2 = __shfl_down_sync(0xffffffffu, b2, off);
        int   z0 = __shfl_down_sync(0xffffffffu, x0, off);
        int   z1 = __shfl_down_sync(0xffffffffu, x1, off);
        int   z2 = __shfl_down_sync(0xffffffffu, x2, off);
        ins3(o0, z0, b0, x0, b1, x1, b2, x2);
        ins3(o1, z1, b0, x0, b1, x1, b2, x2);
        ins3(o2, z2, b0, x0, b1, x1, b2, x2);
    }
    if (lane == 0) {
        sd[wid * 3 + 0] = b0; si[wid * 3 + 0] = x0;
        sd[wid * 3 + 1] = b1; si[wid * 3 + 1] = x1;
        sd[wid * 3 + 2] = b2; si[wid * 3 + 2] = x2;
    }
    __syncthreads();

    if (tid == 0) {
        float r0 = sd[0], r1 = sd[1], r2 = sd[2];
        int   y0 = si[0], y1 = si[1], y2 = si[2];
        #pragma unroll
        for (int e = 3; e < 12; ++e) ins3(sd[e], si[e], r0, y0, r1, y1, r2, y2);

        const float qn = g_qn[q];
        const float kd0 = sqrtf(fmaxf(r0 + qn, 0.f));
        const float kd1 = sqrtf(fmaxf(r1 + qn, 0.f));
        const float kd2 = sqrtf(fmaxf(r2 + qn, 0.f));
        out[q * KNN + 0] = kd0;
        out[q * KNN + 1] = kd1;
        out[q * KNN + 2] = kd2;

        const float w0 = (kd0 == 0.f) ? 1.f : kd0;
        const float w1 = (kd1 == 0.f) ? 1.f : kd1;
        const float w2 = (kd2 == 0.f) ? 1.f : kd2;
        const float* l0 = labels + (size_t)y0 * NCLS;
        const float* l1 = labels + (size_t)y1 * NCLS;
        const float* l2 = labels + (size_t)y2 * NCLS;

        float votes[NCLS];
        #pragma unroll
        for (int cc = 0; cc < NCLS; ++cc)
            votes[cc] = l0[cc] / w0 + l1[cc] / w1 + l2[cc] / w2;

        int am = 0; float bm = votes[0];
        #pragma unroll
        for (int cc = 1; cc < NCLS; ++cc)
            if (votes[cc] > bm) { bm = votes[cc]; am = cc; }

        const bool zero_hit = (kd0 == 0.f);
        float* ro = out + QB * KNN + q * NCLS;
        #pragma unroll
        for (int cc = 0; cc < NCLS; ++cc)
            ro[cc] = zero_hit ? l0[cc] : ((cc == am) ? 1.f : 0.f);
    }
}

// ---------------- launch --------------------------------------------------------
extern "C" void kernel_launch(void* const* d_in, const int* in_sizes, int n_in,
                              void* d_out, int out_size) {
    const float* query = (const float*)d_in[0];
    const float* tf    = (const float*)d_in[1];
    const float* tl    = (const float*)d_in[2];
    float* out = (float*)d_out;
    const int n_elems = in_sizes[1];
    const int N = n_elems / D;
    const int nt = (N + TILE - 1) / TILE;
    const int NP = nt * TILE;

    k_init  <<<1,   32 >>>();
    k_scale <<<888, 216>>>(tf, n_elems);
    k_prep  <<<(NP + 127) / 128, 128>>>(tf, query, N, NP);
    k_hmma  <<<SLABS * GROUPS, 128, SMEM_TOT>>>(N);
    k_reduce<<<QB,  128>>>(tl, out);
}